// round 16
// baseline (speedup 1.0000x reference)
#include <cuda_runtime.h>
#include <cuda_fp16.h>
#include <cstdint>

#define C_DIM 1024
#define C3    3072
#define BB    2
#define TT    2048
#define HH    16
#define MTOT  4096   // BB*TT

// ---------------------------------------------------------------------------
// Scratch buffers (__device__ globals: the sanctioned no-alloc workaround)
// ---------------------------------------------------------------------------
__device__ __half g_qkv16[(size_t)MTOT * C3];    // QKV fp16 (Q pre-scaled by 0.125*log2e)
__device__ __half g_x16[(size_t)MTOT * C_DIM];   // x fp16
__device__ __half g_a16[(size_t)MTOT * C_DIM];   // attn out fp16 (K-major)
__device__ __half g_wq16[(size_t)C3 * C_DIM];    // qkv_w^T fp16 [N=3072][K=1024]
__device__ __half g_wo16[(size_t)C_DIM * C_DIM]; // out_w^T fp16

// ---------------------------------------------------------------------------
// Portable tensor-core helpers (compute_103-safe: ldmatrix / mma.sync / cp.async)
// ---------------------------------------------------------------------------
__device__ __forceinline__ uint32_t smem_u32(const void* p) {
    uint32_t a;
    asm("{ .reg .u64 t; cvta.to.shared.u64 t, %1; cvt.u32.u64 %0, t; }"
        : "=r"(a) : "l"(p));
    return a;
}
#define SWZ128(off) ((off) ^ (((off) >> 3) & 0x70))

__device__ __forceinline__ void ldsm4(uint32_t* r, uint32_t addr) {
    asm volatile("ldmatrix.sync.aligned.m8n8.x4.shared.b16 {%0,%1,%2,%3}, [%4];"
        : "=r"(r[0]), "=r"(r[1]), "=r"(r[2]), "=r"(r[3]) : "r"(addr));
}
__device__ __forceinline__ void ldsm4t(uint32_t* r, uint32_t addr) {
    asm volatile("ldmatrix.sync.aligned.m8n8.x4.trans.shared.b16 {%0,%1,%2,%3}, [%4];"
        : "=r"(r[0]), "=r"(r[1]), "=r"(r[2]), "=r"(r[3]) : "r"(addr));
}
__device__ __forceinline__ void mma_f16(float* d, const uint32_t* a, const uint32_t* b) {
    asm volatile("mma.sync.aligned.m16n8k16.row.col.f32.f16.f16.f32 "
        "{%0,%1,%2,%3}, {%4,%5,%6,%7}, {%8,%9}, {%0,%1,%2,%3};"
        : "+f"(d[0]), "+f"(d[1]), "+f"(d[2]), "+f"(d[3])
        : "r"(a[0]), "r"(a[1]), "r"(a[2]), "r"(a[3]), "r"(b[0]), "r"(b[1]));
}
#define CP16(dst, src)  asm volatile("cp.async.cg.shared.global [%0], [%1], 16;" :: "r"(dst), "l"(src) : "memory")
#define CP_COMMIT()     asm volatile("cp.async.commit_group;" ::: "memory")
#define CP_WAIT0()      asm volatile("cp.async.wait_group 0;" ::: "memory")
#define CP_WAIT1()      asm volatile("cp.async.wait_group 1;" ::: "memory")

__device__ __forceinline__ uint32_t pack_h2(float a, float b) {
    __half2 p = __floats2half2_rn(a, b);
    return *(uint32_t*)&p;
}

// ---------------------------------------------------------------------------
// Fused prepass kernel (one launch): grid-partitioned into
//   [0, 4096)        : x -> fp16
//   [4096, 7168)     : transpose qkv_w -> fp16 [N][K] (grid 96 x 32)
//   [7168, 8192)     : transpose out_w -> fp16 [N][K] (grid 32 x 32)
// ---------------------------------------------------------------------------
__global__ __launch_bounds__(256) void prep_k(
    const float* __restrict__ x,   __half* __restrict__ x16,
    const float* __restrict__ qkv_w, __half* __restrict__ wq16,
    const float* __restrict__ out_w, __half* __restrict__ wo16)
{
    const int bid = blockIdx.x, t = threadIdx.x;
    if (bid < 4096) {
        const int i = bid * 256 + t;                // < MTOT*C_DIM/4
        const float4 v = ((const float4*)x)[i];
        ((__half2*)x16)[i * 2 + 0] = __floats2half2_rn(v.x, v.y);
        ((__half2*)x16)[i * 2 + 1] = __floats2half2_rn(v.z, v.w);
        return;
    }
    __shared__ float tile[32][33];
    const float* in; __half* oT; int N, bx, by;
    if (bid < 7168) {
        const int b2 = bid - 4096;                  // qkv_w: grid 96 x 32
        in = qkv_w; oT = wq16; N = C3;
        bx = b2 % 96; by = b2 / 96;
    } else {
        const int b2 = bid - 7168;                  // out_w: grid 32 x 32
        in = out_w; oT = wo16; N = C_DIM;
        bx = b2 % 32; by = b2 / 32;
    }
    const int n0 = bx * 32, k0 = by * 32;
    const int tx = t & 31, ty = t >> 5;             // 32 x 8
    for (int i = ty; i < 32; i += 8)
        tile[i][tx] = in[(size_t)(k0 + i) * N + n0 + tx];
    __syncthreads();
    for (int i = ty; i < 32; i += 8)
        oT[(size_t)(n0 + i) * 1024 + k0 + tx] = __float2half_rn(tile[tx][i]);
}

// ---------------------------------------------------------------------------
// mma.sync GEMM (R13-best v9, reverted): fp16 single-product, persistent +
// cross-tile pipelined. C tiles 256x128; warp tile 64x64; BK=64; 2-stage.
// mode 0: fp32 out + bias.  mode 1: fp16 out + bias, Q block scaled
//         0.125*log2e (log2-domain softmax downstream).
// ---------------------------------------------------------------------------
#define GA_B      32768                  // A tile: 256 rows x 128B
#define GB_B      16384                  // B tile: 128 rows x 128B
#define GSTAGE_B  (GA_B + GB_B)          // 49152
#define SMEM_GEMM (2 * GSTAGE_B)         // 98304

__global__ __launch_bounds__(256, 1) void gemm_mma(
    const __half* __restrict__ A, const __half* __restrict__ B,
    const float* __restrict__ bias, float* __restrict__ Cf,
    __half* __restrict__ Ch, int Ntot, int mode, int nx, int ntiles)
{
    extern __shared__ __align__(1024) char smg[];
    const uint32_t sb = smem_u32(smg);
    const int t = threadIdx.x, w = t >> 5, lane = t & 31;
    const int wm = (w >> 1) << 6, wn = (w & 1) << 6;
    const int aRow = wm + (lane & 15);
    const int bRow = wn + ((lane >> 4) << 3) + (lane & 7);

    auto fill = [&](const __half* Ab, const __half* Bb, int c, int stg) {
        const int k0 = c << 6;
        const uint32_t stb = sb + stg * GSTAGE_B;
        const __half* s = Ab + k0;
#pragma unroll
        for (int i = 0; i < 8; ++i) {               // A: 2048 x 16B
            const int idx = t + (i << 8);
            const int row = idx >> 3, seg = idx & 7;
            CP16(stb + SWZ128(row * 128 + seg * 16),
                 s + (size_t)row * 1024 + seg * 8);
        }
        const __half* sB = Bb + k0;
#pragma unroll
        for (int i = 0; i < 4; ++i) {               // B: 1024 x 16B
            const int idx = t + (i << 8);
            const int row = idx >> 3, seg = idx & 7;
            CP16(stb + GA_B + SWZ128(row * 128 + seg * 16),
                 sB + (size_t)row * 1024 + seg * 8);
        }
    };

    auto tile_bases = [&](int tid, const __half*& Ab, const __half*& Bb,
                          int& m0, int& n0) {
        m0 = (tid / nx) << 8;
        n0 = (tid % nx) << 7;
        Ab = A + (size_t)m0 * 1024;
        Bb = B + (size_t)n0 * 1024;
    };

    int tile_id = blockIdx.x;
    if (tile_id >= ntiles) return;

    const __half *cA, *cB;
    int m0, n0;
    tile_bases(tile_id, cA, cB, m0, n0);
    fill(cA, cB, 0, 0);
    CP_COMMIT();

    for (;;) {
        const int next_tile = tile_id + gridDim.x;
        const bool has_next = next_tile < ntiles;
        const __half *nA, *nB;
        int nm0, nn0;
        if (has_next) tile_bases(next_tile, nA, nB, nm0, nn0);

        float acc[4][8][4];
#pragma unroll
        for (int i = 0; i < 4; i++)
#pragma unroll
            for (int j = 0; j < 8; j++)
#pragma unroll
                for (int q = 0; q < 4; q++) acc[i][j][q] = 0.f;

        CP_WAIT0();
        __syncthreads();

        for (int c = 0; c < 16; ++c) {
            const int stg = c & 1;
            if (c < 15)        fill(cA, cB, c + 1, stg ^ 1);
            else if (has_next) fill(nA, nB, 0, stg ^ 1);
            CP_COMMIT();

            const uint32_t stA = sb + stg * GSTAGE_B;
            const uint32_t stB = stA + GA_B;

#pragma unroll
            for (int k16 = 0; k16 < 4; ++k16) {
                const int kbA = k16 * 32 + ((lane >> 4) & 1) * 16;
                const int kbB = k16 * 32 + ((lane >> 3) & 1) * 16;

                uint32_t aF[4][4];
#pragma unroll
                for (int mi = 0; mi < 4; ++mi)
                    ldsm4(aF[mi], stA + SWZ128((aRow + mi * 16) * 128 + kbA));

                uint32_t bF[2][4];
                ldsm4(bF[0], stB + SWZ128(bRow * 128 + kbB));
#pragma unroll
                for (int ni = 0; ni < 4; ++ni) {
                    const int cur = ni & 1;
                    if (ni < 3)
                        ldsm4(bF[cur ^ 1],
                              stB + SWZ128((bRow + (ni + 1) * 16) * 128 + kbB));
#pragma unroll
                    for (int mi = 0; mi < 4; ++mi)
#pragma unroll
                        for (int h2 = 0; h2 < 2; ++h2)
                            mma_f16(acc[mi][ni * 2 + h2], aF[mi], &bF[cur][h2 * 2]);
                }
            }
            CP_WAIT0();
            __syncthreads();
        }

        const int g2 = lane >> 2, tg = lane & 3;
        if (mode == 0) {
#pragma unroll
            for (int mi = 0; mi < 4; ++mi) {
                const int row0 = m0 + wm + mi * 16 + g2;
#pragma unroll
                for (int j = 0; j < 8; ++j) {
                    const int col = n0 + wn + j * 8 + tg * 2;
                    const float2 b2 = *(const float2*)&bias[col];
                    const float* d = acc[mi][j];
                    float2 lo2 = { d[0] + b2.x, d[1] + b2.y };
                    float2 hi2 = { d[2] + b2.x, d[3] + b2.y };
                    *(float2*)&Cf[(size_t)row0 * Ntot + col] = lo2;
                    *(float2*)&Cf[(size_t)(row0 + 8) * Ntot + col] = hi2;
                }
            }
        } else {
            // Q block pre-scale folded with log2e for exp2-domain softmax
            const float scale = (n0 < C_DIM) ? 0.18033688f : 1.0f;
#pragma unroll
            for (int mi = 0; mi < 4; ++mi) {
                const int row0 = m0 + wm + mi * 16 + g2;
#pragma unroll
                for (int j = 0; j < 8; ++j) {
                    const int col = n0 + wn + j * 8 + tg * 2;
                    const float2 b2 = *(const float2*)&bias[col];
                    const float* d = acc[mi][j];
                    const size_t o0 = (size_t)row0 * Ntot + col;
                    const size_t o1 = (size_t)(row0 + 8) * Ntot + col;
                    *(uint32_t*)&Ch[o0] =
                        pack_h2((d[0] + b2.x) * scale, (d[1] + b2.y) * scale);
                    *(uint32_t*)&Ch[o1] =
                        pack_h2((d[2] + b2.x) * scale, (d[3] + b2.y) * scale);
                }
            }
        }

        if (!has_next) break;
        tile_id = next_tile;
        cA = nA; cB = nB; m0 = nm0; n0 = nn0;
    }
}

// ---------------------------------------------------------------------------
// Flash attention v8 (fp16, 2 CTAs/SM): 64-key tiles to cut registers
// (sacc 32 regs) and smem (48KB/CTA) so two CTAs co-reside per SM — the
// co-resident CTA's MMAs hide this CTA's softmax and LDSM latency.
// exp2-domain softmax (scores pre-scaled by 0.125*log2e).
// Smem: Q[128][64] (16KB) + 2 stages x {K,V}[64][64] (32KB) = 48KB.
// ---------------------------------------------------------------------------
#define SMEM_ATT2 49152

__global__ __launch_bounds__(256, 2) void attn_mma(
    const __half* __restrict__ qkv, __half* __restrict__ oh)
{
    extern __shared__ __align__(1024) char sma[];
    const uint32_t sb = smem_u32(sma);
    const uint32_t sQ = sb;

    const int t = threadIdx.x, w = t >> 5, lane = t & 31;
    const int g = lane >> 2, tq = lane & 3;
    const int qi = gridDim.x - 1 - blockIdx.x;      // heavy tiles first
    const int bh = blockIdx.y, b = bh >> 4, h = bh & 15;
    const int qbase = qi << 7;
    const size_t brow = (size_t)b * TT;
    const int wm = w << 4;
    const int hcol = h * 64;

    auto fillQ = [&]() {
#pragma unroll
        for (int i = 0; i < 4; ++i) {               // 1024 x 16B
            const int idx = t + (i << 8);
            const int r = idx >> 3, seg = idx & 7;
            CP16(sQ + SWZ128(r * 128 + seg * 16),
                 qkv + (brow + qbase + r) * C3 + hcol + seg * 8);
        }
    };
    auto fillKV = [&](int kt, int buf) {
        const int kb = kt << 6;
        const uint32_t sbase = sb + 16384 + buf * 16384;
#pragma unroll
        for (int i = 0; i < 4; ++i) {               // 1024 x 16B
            const int idx = t + (i << 8);
            const int arr = idx >> 9;               // 0 K, 1 V
            const int r = (idx >> 3) & 63, seg = idx & 7;
            const int colbase = C_DIM + arr * C_DIM + hcol;
            CP16(sbase + arr * 8192 + SWZ128(r * 128 + seg * 16),
                 qkv + (brow + kb + r) * C3 + colbase + seg * 8);
        }
    };

    float oacc[8][4];
#pragma unroll
    for (int j = 0; j < 8; ++j)
#pragma unroll
        for (int q = 0; q < 4; ++q) oacc[j][q] = 0.f;
    float mrow[2] = { -1e30f, -1e30f };
    float lrow[2] = { 0.f, 0.f };

    const int aRow  = wm + (lane & 15);
    const int bRowS = ((lane >> 4) << 3) + (lane & 7);
    const int ntiles = 2 * qi + 2;

    uint32_t aQ[4][4];                               // Q frags, hoisted

    fillQ();
    fillKV(0, 0);
    CP_COMMIT();

    for (int kt = 0; kt < ntiles; ++kt) {
        const int kb = kt << 6;
        const uint32_t sK = sb + 16384 + (kt & 1) * 16384;
        const uint32_t sV = sK + 8192;

        if (kt + 1 < ntiles) {
            fillKV(kt + 1, (kt + 1) & 1);
            CP_COMMIT();
            CP_WAIT1();
        } else {
            CP_WAIT0();
        }
        __syncthreads();

        if (kt == 0) {
#pragma unroll
            for (int k16 = 0; k16 < 4; ++k16) {
                const int kbA = k16 * 32 + ((lane >> 4) & 1) * 16;
                ldsm4(aQ[k16], sQ + SWZ128(aRow * 128 + kbA));
            }
        }

        // ---- S = Q K^T (fp32 accum, log2-scaled), 16 rows x 64 keys ----
        float sacc[8][4];
#pragma unroll
        for (int j = 0; j < 8; ++j)
#pragma unroll
            for (int q = 0; q < 4; ++q) sacc[j][q] = 0.f;

#pragma unroll
        for (int k16 = 0; k16 < 4; ++k16) {
            const int kbB = k16 * 32 + ((lane >> 3) & 1) * 16;
            uint32_t bF[2][4];
            ldsm4(bF[0], sK + SWZ128(bRowS * 128 + kbB));
#pragma unroll
            for (int ni = 0; ni < 4; ++ni) {
                const int cur = ni & 1;
                if (ni < 3)
                    ldsm4(bF[cur ^ 1],
                          sK + SWZ128((bRowS + (ni + 1) * 16) * 128 + kbB));
#pragma unroll
                for (int h2 = 0; h2 < 2; ++h2)
                    mma_f16(sacc[ni * 2 + h2], aQ[k16], &bF[cur][h2 * 2]);
            }
        }

        // ---- causal mask (last two tiles cross the diagonal) ----
        if (kt >= 2 * qi) {
            const int row0 = qbase + wm + g;
#pragma unroll
            for (int j = 0; j < 8; ++j) {
                const int col = kb + j * 8 + tq * 2;
                if (col     > row0)     sacc[j][0] = -1e30f;
                if (col + 1 > row0)     sacc[j][1] = -1e30f;
                if (col     > row0 + 8) sacc[j][2] = -1e30f;
                if (col + 1 > row0 + 8) sacc[j][3] = -1e30f;
            }
        }

        // ---- online softmax in exp2 domain (2 rows/thread) ----
#pragma unroll
        for (int rr = 0; rr < 2; ++rr) {
            const int i0 = rr * 2;
            float mt = -1e30f;
#pragma unroll
            for (int j = 0; j < 8; ++j)
                mt = fmaxf(mt, fmaxf(sacc[j][i0], sacc[j][i0 + 1]));
            mt = fmaxf(mt, __shfl_xor_sync(0xffffffffu, mt, 1));
            mt = fmaxf(mt, __shfl_xor_sync(0xffffffffu, mt, 2));
            const float mn = fmaxf(mrow[rr], mt);
            const float alpha = exp2f(mrow[rr] - mn);
            mrow[rr] = mn;
            float ps = 0.f;
#pragma unroll
            for (int j = 0; j < 8; ++j) {
                const float p0 = exp2f(sacc[j][i0] - mn);
                const float p1 = exp2f(sacc[j][i0 + 1] - mn);
                sacc[j][i0] = p0; sacc[j][i0 + 1] = p1;
                ps += p0 + p1;
            }
            ps += __shfl_xor_sync(0xffffffffu, ps, 1);
            ps += __shfl_xor_sync(0xffffffffu, ps, 2);
            lrow[rr] = lrow[rr] * alpha + ps;
#pragma unroll
            for (int j = 0; j < 8; ++j) {
                oacc[j][i0] *= alpha;
                oacc[j][i0 + 1] *= alpha;
            }
        }

        // ---- O += P V (P packed fp16 register-direct; V via ldmatrix.trans) ----
#pragma unroll
        for (int kk = 0; kk < 4; ++kk) {
            const float* s0 = sacc[2 * kk];
            const float* s1 = sacc[2 * kk + 1];
            uint32_t aP[4];
            aP[0] = pack_h2(s0[0], s0[1]);
            aP[1] = pack_h2(s0[2], s0[3]);
            aP[2] = pack_h2(s1[0], s1[1]);
            aP[3] = pack_h2(s1[2], s1[3]);
            const int vr = kk * 16 + (lane & 15);
            const int vc = ((lane >> 4) & 1) * 16;
            uint32_t vF[4][4];
#pragma unroll
            for (int ni = 0; ni < 4; ++ni)
                ldsm4t(vF[ni], sV + SWZ128(vr * 128 + ni * 32 + vc));
#pragma unroll
            for (int ni = 0; ni < 4; ++ni)
#pragma unroll
                for (int h2 = 0; h2 < 2; ++h2)
                    mma_f16(oacc[ni * 2 + h2], aP, &vF[ni][h2 * 2]);
        }
        __syncthreads();
    }

    // ---- epilogue: normalize, store fp16 (K-major [M][1024]) ----
    const float inv0 = 1.f / lrow[0];
    const float inv1 = 1.f / lrow[1];
    const int row0 = qbase + wm + g;
#pragma unroll
    for (int j = 0; j < 8; ++j) {
        const int col = hcol + j * 8 + tq * 2;
        const size_t o0 = (brow + row0) * C_DIM + col;
        const size_t o1 = (brow + row0 + 8) * C_DIM + col;
        *(uint32_t*)&oh[o0] = pack_h2(oacc[j][0] * inv0, oacc[j][1] * inv0);
        *(uint32_t*)&oh[o1] = pack_h2(oacc[j][2] * inv1, oacc[j][3] * inv1);
    }
}

// ---------------------------------------------------------------------------
extern "C" void kernel_launch(void* const* d_in, const int* in_sizes, int n_in,
                              void* d_out, int out_size)
{
    const float* x      = (const float*)d_in[0];
    const float* qkv_w  = (const float*)d_in[1];
    const float* qkv_b  = (const float*)d_in[2];
    const float* out_w  = (const float*)d_in[3];
    const float* out_b  = (const float*)d_in[4];
    float* out = (float*)d_out;

    __half *qv16, *x16, *a16, *wq16, *wo16;
    cudaGetSymbolAddress((void**)&qv16, g_qkv16);
    cudaGetSymbolAddress((void**)&x16, g_x16);
    cudaGetSymbolAddress((void**)&a16, g_a16);
    cudaGetSymbolAddress((void**)&wq16, g_wq16);
    cudaGetSymbolAddress((void**)&wo16, g_wo16);

    cudaFuncSetAttribute(gemm_mma, cudaFuncAttributeMaxDynamicSharedMemorySize, SMEM_GEMM);
    cudaFuncSetAttribute(attn_mma, cudaFuncAttributeMaxDynamicSharedMemorySize, SMEM_ATT2);

    // Fused prepasses (one launch): x -> fp16, weights transposed -> fp16
    prep_k<<<8192, 256>>>(x, x16, qkv_w, wq16, out_w, wo16);

    // 1) QKV projection -> fp16 output (Q pre-scaled by 0.125*log2e)
    gemm_mma<<<148, 256, SMEM_GEMM>>>(
        x16, wq16, qkv_b, nullptr, qv16, C3, 1,
        C3 / 128, (C3 / 128) * (MTOT / 256));

    // 2) Causal MHA (fp16, exp2 softmax, 64-key tiles, 2 CTAs/SM)
    attn_mma<<<dim3(TT / 128, BB * HH), 256, SMEM_ATT2>>>(qv16, a16);

    // 3) Output projection -> fp32 final output
    gemm_mma<<<148, 256, SMEM_GEMM>>>(
        a16, wo16, out_b, out, nullptr, C_DIM, 0,
        C_DIM / 128, (C_DIM / 128) * (MTOT / 256));
}

// round 17
// speedup vs baseline: 1.0446x; 1.0446x over previous
#include <cuda_runtime.h>
#include <cuda_fp16.h>
#include <cstdint>

#define C_DIM 1024
#define C3    3072
#define BB    2
#define TT    2048
#define HH    16
#define MTOT  4096   // BB*TT

// ---------------------------------------------------------------------------
// Scratch buffers (__device__ globals: the sanctioned no-alloc workaround)
// ---------------------------------------------------------------------------
__device__ __half g_qkv16[(size_t)MTOT * C3];    // QKV fp16 (Q pre-scaled by 0.125*log2e)
__device__ __half g_x16[(size_t)MTOT * C_DIM];   // x fp16
__device__ __half g_a16[(size_t)MTOT * C_DIM];   // attn out fp16 (K-major)
__device__ __half g_wq16[(size_t)C3 * C_DIM];    // qkv_w^T fp16 [N=3072][K=1024]
__device__ __half g_wo16[(size_t)C_DIM * C_DIM]; // out_w^T fp16

// ---------------------------------------------------------------------------
// Portable tensor-core helpers (compute_103-safe: ldmatrix / mma.sync / cp.async)
// ---------------------------------------------------------------------------
__device__ __forceinline__ uint32_t smem_u32(const void* p) {
    uint32_t a;
    asm("{ .reg .u64 t; cvta.to.shared.u64 t, %1; cvt.u32.u64 %0, t; }"
        : "=r"(a) : "l"(p));
    return a;
}
#define SWZ128(off) ((off) ^ (((off) >> 3) & 0x70))

__device__ __forceinline__ void ldsm4(uint32_t* r, uint32_t addr) {
    asm volatile("ldmatrix.sync.aligned.m8n8.x4.shared.b16 {%0,%1,%2,%3}, [%4];"
        : "=r"(r[0]), "=r"(r[1]), "=r"(r[2]), "=r"(r[3]) : "r"(addr));
}
__device__ __forceinline__ void ldsm4t(uint32_t* r, uint32_t addr) {
    asm volatile("ldmatrix.sync.aligned.m8n8.x4.trans.shared.b16 {%0,%1,%2,%3}, [%4];"
        : "=r"(r[0]), "=r"(r[1]), "=r"(r[2]), "=r"(r[3]) : "r"(addr));
}
__device__ __forceinline__ void mma_f16(float* d, const uint32_t* a, const uint32_t* b) {
    asm volatile("mma.sync.aligned.m16n8k16.row.col.f32.f16.f16.f32 "
        "{%0,%1,%2,%3}, {%4,%5,%6,%7}, {%8,%9}, {%0,%1,%2,%3};"
        : "+f"(d[0]), "+f"(d[1]), "+f"(d[2]), "+f"(d[3])
        : "r"(a[0]), "r"(a[1]), "r"(a[2]), "r"(a[3]), "r"(b[0]), "r"(b[1]));
}
#define CP16(dst, src)  asm volatile("cp.async.cg.shared.global [%0], [%1], 16;" :: "r"(dst), "l"(src) : "memory")
#define CP_COMMIT()     asm volatile("cp.async.commit_group;" ::: "memory")
#define CP_WAIT0()      asm volatile("cp.async.wait_group 0;" ::: "memory")
#define CP_WAIT1()      asm volatile("cp.async.wait_group 1;" ::: "memory")

__device__ __forceinline__ uint32_t pack_h2(float a, float b) {
    __half2 p = __floats2half2_rn(a, b);
    return *(uint32_t*)&p;
}

// ---------------------------------------------------------------------------
// Fused prepass kernel (one launch): grid-partitioned into
//   [0, 4096)        : x -> fp16
//   [4096, 7168)     : transpose qkv_w -> fp16 [N][K] (grid 96 x 32)
//   [7168, 8192)     : transpose out_w -> fp16 [N][K] (grid 32 x 32)
// ---------------------------------------------------------------------------
__global__ __launch_bounds__(256) void prep_k(
    const float* __restrict__ x,   __half* __restrict__ x16,
    const float* __restrict__ qkv_w, __half* __restrict__ wq16,
    const float* __restrict__ out_w, __half* __restrict__ wo16)
{
    const int bid = blockIdx.x, t = threadIdx.x;
    if (bid < 4096) {
        const int i = bid * 256 + t;                // < MTOT*C_DIM/4
        const float4 v = ((const float4*)x)[i];
        ((__half2*)x16)[i * 2 + 0] = __floats2half2_rn(v.x, v.y);
        ((__half2*)x16)[i * 2 + 1] = __floats2half2_rn(v.z, v.w);
        return;
    }
    __shared__ float tile[32][33];
    const float* in; __half* oT; int N, bx, by;
    if (bid < 7168) {
        const int b2 = bid - 4096;                  // qkv_w: grid 96 x 32
        in = qkv_w; oT = wq16; N = C3;
        bx = b2 % 96; by = b2 / 96;
    } else {
        const int b2 = bid - 7168;                  // out_w: grid 32 x 32
        in = out_w; oT = wo16; N = C_DIM;
        bx = b2 % 32; by = b2 / 32;
    }
    const int n0 = bx * 32, k0 = by * 32;
    const int tx = t & 31, ty = t >> 5;             // 32 x 8
    for (int i = ty; i < 32; i += 8)
        tile[i][tx] = in[(size_t)(k0 + i) * N + n0 + tx];
    __syncthreads();
    for (int i = ty; i < 32; i += 8)
        oT[(size_t)(n0 + i) * 1024 + k0 + tx] = __float2half_rn(tile[tx][i]);
}

// ---------------------------------------------------------------------------
// mma.sync GEMM (R13-best v9): fp16 single-product, persistent + cross-tile
// pipelined. C tiles 256x128; warp tile 64x64; BK=64; 2-stage cp.async.
// mode 0: fp32 out + bias.  mode 1: fp16 out + bias, Q block scaled
//         0.125*log2e (log2-domain softmax downstream).
// ---------------------------------------------------------------------------
#define GA_B      32768                  // A tile: 256 rows x 128B
#define GB_B      16384                  // B tile: 128 rows x 128B
#define GSTAGE_B  (GA_B + GB_B)          // 49152
#define SMEM_GEMM (2 * GSTAGE_B)         // 98304

__global__ __launch_bounds__(256, 1) void gemm_mma(
    const __half* __restrict__ A, const __half* __restrict__ B,
    const float* __restrict__ bias, float* __restrict__ Cf,
    __half* __restrict__ Ch, int Ntot, int mode, int nx, int ntiles)
{
    extern __shared__ __align__(1024) char smg[];
    const uint32_t sb = smem_u32(smg);
    const int t = threadIdx.x, w = t >> 5, lane = t & 31;
    const int wm = (w >> 1) << 6, wn = (w & 1) << 6;
    const int aRow = wm + (lane & 15);
    const int bRow = wn + ((lane >> 4) << 3) + (lane & 7);

    auto fill = [&](const __half* Ab, const __half* Bb, int c, int stg) {
        const int k0 = c << 6;
        const uint32_t stb = sb + stg * GSTAGE_B;
        const __half* s = Ab + k0;
#pragma unroll
        for (int i = 0; i < 8; ++i) {               // A: 2048 x 16B
            const int idx = t + (i << 8);
            const int row = idx >> 3, seg = idx & 7;
            CP16(stb + SWZ128(row * 128 + seg * 16),
                 s + (size_t)row * 1024 + seg * 8);
        }
        const __half* sB = Bb + k0;
#pragma unroll
        for (int i = 0; i < 4; ++i) {               // B: 1024 x 16B
            const int idx = t + (i << 8);
            const int row = idx >> 3, seg = idx & 7;
            CP16(stb + GA_B + SWZ128(row * 128 + seg * 16),
                 sB + (size_t)row * 1024 + seg * 8);
        }
    };

    auto tile_bases = [&](int tid, const __half*& Ab, const __half*& Bb,
                          int& m0, int& n0) {
        m0 = (tid / nx) << 8;
        n0 = (tid % nx) << 7;
        Ab = A + (size_t)m0 * 1024;
        Bb = B + (size_t)n0 * 1024;
    };

    int tile_id = blockIdx.x;
    if (tile_id >= ntiles) return;

    const __half *cA, *cB;
    int m0, n0;
    tile_bases(tile_id, cA, cB, m0, n0);
    fill(cA, cB, 0, 0);
    CP_COMMIT();

    for (;;) {
        const int next_tile = tile_id + gridDim.x;
        const bool has_next = next_tile < ntiles;
        const __half *nA, *nB;
        int nm0, nn0;
        if (has_next) tile_bases(next_tile, nA, nB, nm0, nn0);

        float acc[4][8][4];
#pragma unroll
        for (int i = 0; i < 4; i++)
#pragma unroll
            for (int j = 0; j < 8; j++)
#pragma unroll
                for (int q = 0; q < 4; q++) acc[i][j][q] = 0.f;

        CP_WAIT0();
        __syncthreads();

        for (int c = 0; c < 16; ++c) {
            const int stg = c & 1;
            if (c < 15)        fill(cA, cB, c + 1, stg ^ 1);
            else if (has_next) fill(nA, nB, 0, stg ^ 1);
            CP_COMMIT();

            const uint32_t stA = sb + stg * GSTAGE_B;
            const uint32_t stB = stA + GA_B;

#pragma unroll
            for (int k16 = 0; k16 < 4; ++k16) {
                const int kbA = k16 * 32 + ((lane >> 4) & 1) * 16;
                const int kbB = k16 * 32 + ((lane >> 3) & 1) * 16;

                uint32_t aF[4][4];
#pragma unroll
                for (int mi = 0; mi < 4; ++mi)
                    ldsm4(aF[mi], stA + SWZ128((aRow + mi * 16) * 128 + kbA));

                uint32_t bF[2][4];
                ldsm4(bF[0], stB + SWZ128(bRow * 128 + kbB));
#pragma unroll
                for (int ni = 0; ni < 4; ++ni) {
                    const int cur = ni & 1;
                    if (ni < 3)
                        ldsm4(bF[cur ^ 1],
                              stB + SWZ128((bRow + (ni + 1) * 16) * 128 + kbB));
#pragma unroll
                    for (int mi = 0; mi < 4; ++mi)
#pragma unroll
                        for (int h2 = 0; h2 < 2; ++h2)
                            mma_f16(acc[mi][ni * 2 + h2], aF[mi], &bF[cur][h2 * 2]);
                }
            }
            CP_WAIT0();
            __syncthreads();
        }

        const int g2 = lane >> 2, tg = lane & 3;
        if (mode == 0) {
#pragma unroll
            for (int mi = 0; mi < 4; ++mi) {
                const int row0 = m0 + wm + mi * 16 + g2;
#pragma unroll
                for (int j = 0; j < 8; ++j) {
                    const int col = n0 + wn + j * 8 + tg * 2;
                    const float2 b2 = *(const float2*)&bias[col];
                    const float* d = acc[mi][j];
                    float2 lo2 = { d[0] + b2.x, d[1] + b2.y };
                    float2 hi2 = { d[2] + b2.x, d[3] + b2.y };
                    *(float2*)&Cf[(size_t)row0 * Ntot + col] = lo2;
                    *(float2*)&Cf[(size_t)(row0 + 8) * Ntot + col] = hi2;
                }
            }
        } else {
            // Q block pre-scale folded with log2e for exp2-domain softmax
            const float scale = (n0 < C_DIM) ? 0.18033688f : 1.0f;
#pragma unroll
            for (int mi = 0; mi < 4; ++mi) {
                const int row0 = m0 + wm + mi * 16 + g2;
#pragma unroll
                for (int j = 0; j < 8; ++j) {
                    const int col = n0 + wn + j * 8 + tg * 2;
                    const float2 b2 = *(const float2*)&bias[col];
                    const float* d = acc[mi][j];
                    const size_t o0 = (size_t)row0 * Ntot + col;
                    const size_t o1 = (size_t)(row0 + 8) * Ntot + col;
                    *(uint32_t*)&Ch[o0] =
                        pack_h2((d[0] + b2.x) * scale, (d[1] + b2.y) * scale);
                    *(uint32_t*)&Ch[o1] =
                        pack_h2((d[2] + b2.x) * scale, (d[3] + b2.y) * scale);
                }
            }
        }

        if (!has_next) break;
        tile_id = next_tile;
        cA = nA; cB = nB; m0 = nm0; n0 = nn0;
    }
}

// ---------------------------------------------------------------------------
// Flash attention v9: R13 structure (128-key tiles, 1 CTA/SM) with
// softmax surgery:
//  - h2exp2 packed fp16 exp (16 MUFU instead of 32; output IS the PV A-frag)
//  - row sum ell computed by an extra MMA vs an all-ones B fragment
//    (accumulated in lacc, alpha-rescaled like O; no sum loop, no shfl)
// Smem: Q[128][64] (16KB) + 2 stages x {K,V}[128][64] (64KB) = 80KB.
// ---------------------------------------------------------------------------
#define SMEM_ATT2 81920

__global__ __launch_bounds__(256) void attn_mma(
    const __half* __restrict__ qkv, __half* __restrict__ oh)
{
    extern __shared__ __align__(1024) char sma[];
    const uint32_t sb = smem_u32(sma);
    const uint32_t sQ = sb;

    const int t = threadIdx.x, w = t >> 5, lane = t & 31;
    const int g = lane >> 2, tq = lane & 3;
    const int qi = gridDim.x - 1 - blockIdx.x;      // heavy tiles first
    const int bh = blockIdx.y, b = bh >> 4, h = bh & 15;
    const int qbase = qi << 7;
    const size_t brow = (size_t)b * TT;
    const int wm = w << 4;
    const int hcol = h * 64;

    auto fillQ = [&]() {
#pragma unroll
        for (int i = 0; i < 4; ++i) {               // 1024 x 16B
            const int idx = t + (i << 8);
            const int r = idx >> 3, seg = idx & 7;
            CP16(sQ + SWZ128(r * 128 + seg * 16),
                 qkv + (brow + qbase + r) * C3 + hcol + seg * 8);
        }
    };
    auto fillKV = [&](int kt, int buf) {
        const int kb = kt << 7;
        const uint32_t sbase = sb + 16384 + buf * 32768;
#pragma unroll
        for (int i = 0; i < 8; ++i) {               // 2048 x 16B
            const int idx = t + (i << 8);
            const int arr = idx >> 10;              // 0 K, 1 V
            const int r = (idx >> 3) & 127, seg = idx & 7;
            const int colbase = C_DIM + arr * C_DIM + hcol;
            CP16(sbase + arr * 16384 + SWZ128(r * 128 + seg * 16),
                 qkv + (brow + kb + r) * C3 + colbase + seg * 8);
        }
    };

    float oacc[8][4];
#pragma unroll
    for (int j = 0; j < 8; ++j)
#pragma unroll
        for (int q = 0; q < 4; ++q) oacc[j][q] = 0.f;
    float lacc[4] = { 0.f, 0.f, 0.f, 0.f };         // row sums via ones-MMA
    float mrow[2] = { -1e30f, -1e30f };

    const uint32_t ONE2 = 0x3C003C00u;              // (1.0h, 1.0h)
    uint32_t bOne[2] = { ONE2, ONE2 };

    const int aRow  = wm + (lane & 15);
    const int bRowS = ((lane >> 4) << 3) + (lane & 7);
    const int ntiles = qi + 1;

    uint32_t aQ[4][4];                               // Q frags, hoisted

    fillQ();
    fillKV(0, 0);
    CP_COMMIT();

    for (int kt = 0; kt < ntiles; ++kt) {
        const int kb = kt << 7;
        const uint32_t sK = sb + 16384 + (kt & 1) * 32768;
        const uint32_t sV = sK + 16384;

        if (kt + 1 < ntiles) {
            fillKV(kt + 1, (kt + 1) & 1);
            CP_COMMIT();
            CP_WAIT1();
        } else {
            CP_WAIT0();
        }
        __syncthreads();

        if (kt == 0) {
#pragma unroll
            for (int k16 = 0; k16 < 4; ++k16) {
                const int kbA = k16 * 32 + ((lane >> 4) & 1) * 16;
                ldsm4(aQ[k16], sQ + SWZ128(aRow * 128 + kbA));
            }
        }

        // ---- S = Q K^T (fp32 accum, log2-scaled), 16 rows x 128 keys ----
        float sacc[16][4];
#pragma unroll
        for (int j = 0; j < 16; ++j)
#pragma unroll
            for (int q = 0; q < 4; ++q) sacc[j][q] = 0.f;

#pragma unroll
        for (int k16 = 0; k16 < 4; ++k16) {
            const int kbB = k16 * 32 + ((lane >> 3) & 1) * 16;
            uint32_t bF[2][4];
            ldsm4(bF[0], sK + SWZ128(bRowS * 128 + kbB));
#pragma unroll
            for (int ni = 0; ni < 8; ++ni) {
                const int cur = ni & 1;
                if (ni < 7)
                    ldsm4(bF[cur ^ 1],
                          sK + SWZ128((bRowS + (ni + 1) * 16) * 128 + kbB));
#pragma unroll
                for (int h2 = 0; h2 < 2; ++h2)
                    mma_f16(sacc[ni * 2 + h2], aQ[k16], &bF[cur][h2 * 2]);
            }
        }

        // ---- causal mask (exactly one diagonal tile: kt == qi) ----
        if (kt == qi) {
            const int row0 = qbase + wm + g;
#pragma unroll
            for (int j = 0; j < 16; ++j) {
                const int col = kb + j * 8 + tq * 2;
                if (col     > row0)     sacc[j][0] = -1e30f;
                if (col + 1 > row0)     sacc[j][1] = -1e30f;
                if (col     > row0 + 8) sacc[j][2] = -1e30f;
                if (col + 1 > row0 + 8) sacc[j][3] = -1e30f;
            }
        }

        // ---- online softmax (exp2 domain; packed fp16 p; no sum loop) ----
        uint32_t pP[16][2];                          // packed p: [j][row pair]
#pragma unroll
        for (int rr = 0; rr < 2; ++rr) {
            const int i0 = rr * 2;
            float mt = -1e30f;
#pragma unroll
            for (int j = 0; j < 16; ++j)
                mt = fmaxf(mt, fmaxf(sacc[j][i0], sacc[j][i0 + 1]));
            mt = fmaxf(mt, __shfl_xor_sync(0xffffffffu, mt, 1));
            mt = fmaxf(mt, __shfl_xor_sync(0xffffffffu, mt, 2));
            const float mn = fmaxf(mrow[rr], mt);
            const float alpha = exp2f(mrow[rr] - mn);
            mrow[rr] = mn;
#pragma unroll
            for (int j = 0; j < 16; ++j) {
                __half2 d2 = __floats2half2_rn(sacc[j][i0] - mn,
                                               sacc[j][i0 + 1] - mn);
                __half2 p2 = h2exp2(d2);
                pP[j][rr] = *(uint32_t*)&p2;
            }
            lacc[i0]     *= alpha;
            lacc[i0 + 1] *= alpha;
#pragma unroll
            for (int j = 0; j < 8; ++j) {
                oacc[j][i0] *= alpha;
                oacc[j][i0 + 1] *= alpha;
            }
        }

        // ---- O += P V, ell += P 1 (V via ldmatrix.trans) ----
#pragma unroll
        for (int kk = 0; kk < 8; ++kk) {
            uint32_t aP[4];
            aP[0] = pP[2 * kk][0];
            aP[1] = pP[2 * kk][1];
            aP[2] = pP[2 * kk + 1][0];
            aP[3] = pP[2 * kk + 1][1];
            const int vr = kk * 16 + (lane & 15);
            const int vc = ((lane >> 4) & 1) * 16;
            uint32_t vF[4][4];
#pragma unroll
            for (int ni = 0; ni < 4; ++ni)
                ldsm4t(vF[ni], sV + SWZ128(vr * 128 + ni * 32 + vc));
            mma_f16(lacc, aP, bOne);                 // row sums
#pragma unroll
            for (int ni = 0; ni < 4; ++ni)
#pragma unroll
                for (int h2 = 0; h2 < 2; ++h2)
                    mma_f16(oacc[ni * 2 + h2], aP, &vF[ni][h2 * 2]);
        }
        __syncthreads();
    }

    // ---- epilogue: normalize (lacc cols all equal row sum), store fp16 ----
    const float inv0 = 1.f / lacc[0];
    const float inv1 = 1.f / lacc[2];
    const int row0 = qbase + wm + g;
#pragma unroll
    for (int j = 0; j < 8; ++j) {
        const int col = hcol + j * 8 + tq * 2;
        const size_t o0 = (brow + row0) * C_DIM + col;
        const size_t o1 = (brow + row0 + 8) * C_DIM + col;
        *(uint32_t*)&oh[o0] = pack_h2(oacc[j][0] * inv0, oacc[j][1] * inv0);
        *(uint32_t*)&oh[o1] = pack_h2(oacc[j][2] * inv1, oacc[j][3] * inv1);
    }
}

// ---------------------------------------------------------------------------
extern "C" void kernel_launch(void* const* d_in, const int* in_sizes, int n_in,
                              void* d_out, int out_size)
{
    const float* x      = (const float*)d_in[0];
    const float* qkv_w  = (const float*)d_in[1];
    const float* qkv_b  = (const float*)d_in[2];
    const float* out_w  = (const float*)d_in[3];
    const float* out_b  = (const float*)d_in[4];
    float* out = (float*)d_out;

    __half *qv16, *x16, *a16, *wq16, *wo16;
    cudaGetSymbolAddress((void**)&qv16, g_qkv16);
    cudaGetSymbolAddress((void**)&x16, g_x16);
    cudaGetSymbolAddress((void**)&a16, g_a16);
    cudaGetSymbolAddress((void**)&wq16, g_wq16);
    cudaGetSymbolAddress((void**)&wo16, g_wo16);

    cudaFuncSetAttribute(gemm_mma, cudaFuncAttributeMaxDynamicSharedMemorySize, SMEM_GEMM);
    cudaFuncSetAttribute(attn_mma, cudaFuncAttributeMaxDynamicSharedMemorySize, SMEM_ATT2);

    // Fused prepasses (one launch): x -> fp16, weights transposed -> fp16
    prep_k<<<8192, 256>>>(x, x16, qkv_w, wq16, out_w, wo16);

    // 1) QKV projection -> fp16 output (Q pre-scaled by 0.125*log2e)
    gemm_mma<<<148, 256, SMEM_GEMM>>>(
        x16, wq16, qkv_b, nullptr, qv16, C3, 1,
        C3 / 128, (C3 / 128) * (MTOT / 256));

    // 2) Causal MHA (fp16, packed-exp2 softmax, MMA row sums)
    attn_mma<<<dim3(TT / 128, BB * HH), 256, SMEM_ATT2>>>(qv16, a16);

    // 3) Output projection -> fp32 final output
    gemm_mma<<<148, 256, SMEM_GEMM>>>(
        a16, wo16, out_b, out, nullptr, C_DIM, 0,
        C_DIM / 128, (C_DIM / 128) * (MTOT / 256));
}